// round 14
// baseline (speedup 1.0000x reference)
#include <cuda_runtime.h>
#include <cuda_bf16.h>
#include <stdint.h>
#include <math.h>

#define SEQ    256
#define BATCH  256
#define KD     1024
#define ND     1024
#define MX     (SEQ * BATCH)
#define HN     (BATCH * ND)
#define NCTA   128

// ---------------- device scratch ------------------------------------------
static __device__ float          g_gx[(size_t)3 * MX * ND];
static __device__ __nv_bfloat16  g_axhi[(size_t)MX * KD];
static __device__ __nv_bfloat16  g_axlo[(size_t)MX * KD];
static __device__ __nv_bfloat16  g_wxhi[(size_t)3 * ND * KD];
static __device__ __nv_bfloat16  g_wxlo[(size_t)3 * ND * KD];
static __device__ __nv_bfloat16  g_wph[(size_t)3 * ND * KD];
static __device__ __nv_bfloat16  g_wpl[(size_t)3 * ND * KD];
static __device__ __nv_bfloat16  g_hhi[(size_t)BATCH * KD];
static __device__ __nv_bfloat16  g_hlo[(size_t)BATCH * KD];
static __device__ unsigned g_cntArr[128];
static __device__ unsigned g_genArr[128];

__device__ __forceinline__ uint32_t smem_u32(const void* p) {
    uint32_t a;
    asm("{ .reg .u64 t; cvta.to.shared.u64 t, %1; cvt.u32.u64 %0, t; }"
        : "=r"(a) : "l"(p));
    return a;
}
static __device__ __forceinline__ uint32_t sw128(uint32_t b) {
    return b ^ ((b >> 3) & 0x70);
}
__device__ __forceinline__ void ldsm4(uint32_t (&d)[4], uint32_t addr) {
    asm volatile("ldmatrix.sync.aligned.m8n8.x4.shared.b16 {%0,%1,%2,%3}, [%4];"
                 : "=r"(d[0]), "=r"(d[1]), "=r"(d[2]), "=r"(d[3]) : "r"(addr));
}
__device__ __forceinline__ void mma16816(float (&c)[4], const uint32_t (&a)[4],
                                         uint32_t b0, uint32_t b1) {
    asm volatile("mma.sync.aligned.m16n8k16.row.col.f32.bf16.bf16.f32 "
                 "{%0,%1,%2,%3}, {%4,%5,%6,%7}, {%8,%9}, {%0,%1,%2,%3};"
                 : "+f"(c[0]), "+f"(c[1]), "+f"(c[2]), "+f"(c[3])
                 : "r"(a[0]), "r"(a[1]), "r"(a[2]), "r"(a[3]), "r"(b0), "r"(b1));
}
__device__ __forceinline__ void cpa16(uint32_t smaddr, const void* g) {
    asm volatile("cp.async.cg.shared.global [%0], [%1], 16;" :: "r"(smaddr), "l"(g));
}
#define CPA_COMMIT() asm volatile("cp.async.commit_group;" ::: "memory")
template<int N> __device__ __forceinline__ void cp_wait() {
    asm volatile("cp.async.wait_group %0;" :: "n"(N) : "memory");
}
__device__ __forceinline__ float sigm(float v) { return 1.0f / (1.0f + expf(-v)); }

// ---------------- phase 0: splits / packing --------------------------------
__device__ __forceinline__ void split4(float4 v, __nv_bfloat16* hi,
                                       __nv_bfloat16* lo, size_t idx4) {
    __nv_bfloat16 h0 = __float2bfloat16_rn(v.x);
    __nv_bfloat16 h1 = __float2bfloat16_rn(v.y);
    __nv_bfloat16 h2 = __float2bfloat16_rn(v.z);
    __nv_bfloat16 h3 = __float2bfloat16_rn(v.w);
    __nv_bfloat16 l0 = __float2bfloat16_rn(v.x - __bfloat162float(h0));
    __nv_bfloat16 l1 = __float2bfloat16_rn(v.y - __bfloat162float(h1));
    __nv_bfloat16 l2 = __float2bfloat16_rn(v.z - __bfloat162float(h2));
    __nv_bfloat16 l3 = __float2bfloat16_rn(v.w - __bfloat162float(h3));
    __nv_bfloat162* hp = (__nv_bfloat162*)(hi + idx4 * 4);
    __nv_bfloat162* lp = (__nv_bfloat162*)(lo + idx4 * 4);
    hp[0] = __nv_bfloat162(h0, h1); hp[1] = __nv_bfloat162(h2, h3);
    lp[0] = __nv_bfloat162(l0, l1); lp[1] = __nv_bfloat162(l2, l3);
}

__global__ __launch_bounds__(256)
void split_bf16(const float* __restrict__ src, __nv_bfloat16* __restrict__ hi,
                __nv_bfloat16* __restrict__ lo, int n4)
{
    int i = blockIdx.x * 256 + threadIdx.x;
    if (i >= n4) return;
    split4(((const float4*)src)[i], hi, lo, (size_t)i);
}

__global__ __launch_bounds__(256)
void split3_w(const float* __restrict__ W0, const float* __restrict__ W1,
              const float* __restrict__ W2,
              __nv_bfloat16* __restrict__ hi, __nv_bfloat16* __restrict__ lo)
{
    const int per = ND * KD / 4;
    int i = blockIdx.x * 256 + threadIdx.x;
    if (i >= 3 * per) return;
    int g = i / per, r = i - g * per;
    const float* W = (g == 0) ? W0 : (g == 1) ? W1 : W2;
    split4(*(const float4*)(W + (size_t)r * 4), hi, lo, (size_t)i);
}

__global__ __launch_bounds__(256)
void pack3_wh(const float* __restrict__ W0, const float* __restrict__ W1,
              const float* __restrict__ W2,
              __nv_bfloat16* __restrict__ ph, __nv_bfloat16* __restrict__ pl)
{
    const int per = ND * KD / 4;
    int i = blockIdx.x * 256 + threadIdx.x;
    if (i >= 3 * per) return;
    int g = i / per, r = i - g * per;
    const float* W = (g == 0) ? W0 : (g == 1) ? W1 : W2;
    int n  = r >> 8;
    int k4 = r & 255;
    float4 v = *(const float4*)(W + (size_t)n * KD + k4 * 4);
    size_t drow = (size_t)((n >> 5) * 96 + g * 32 + (n & 31));
    split4(v, ph, pl, drow * (KD / 4) + k4);
}

// ---------------- phase 1: HMMA GEMM (round-8 proven, unchanged) ------------
#define P1_STG 32768

__global__ __launch_bounds__(256)
void gemm_hmma(const float* __restrict__ b0p, const float* __restrict__ b1p,
               const float* __restrict__ b2p)
{
    extern __shared__ char sm[];
    const uint32_t smb = smem_u32(sm);
    const int tid  = threadIdx.x;
    const int lane = tid & 31;
    const int w    = tid >> 5;
    const int wm   = w & 3;
    const int wn   = w >> 2;
    const int n0   = blockIdx.x * 128;
    const int m0   = blockIdx.y * 128;
    const int g    = blockIdx.z;

    const __nv_bfloat16* ahi = g_axhi + (size_t)m0 * KD;
    const __nv_bfloat16* alo = g_axlo + (size_t)m0 * KD;
    const __nv_bfloat16* whi = g_wxhi + (size_t)g * ND * KD + (size_t)n0 * KD;
    const __nv_bfloat16* wlo = g_wxlo + (size_t)g * ND * KD + (size_t)n0 * KD;

    auto issue = [&](int ck) {
        int p = ck >> 4, kb = (ck & 15) * 64;
        const __nv_bfloat16* As = (p < 2) ? ahi : alo;
        const __nv_bfloat16* Bs = (p == 1) ? wlo : whi;
        uint32_t stg = smb + (ck % 3) * P1_STG;
        #pragma unroll
        for (int i = 0; i < 4; i++) {
            int q = tid + i * 256; int row = q >> 3, kq = q & 7;
            cpa16(stg + sw128((uint32_t)(row * 128 + kq * 16)),
                  As + (size_t)row * KD + kb + kq * 8);
        }
        #pragma unroll
        for (int i = 0; i < 4; i++) {
            int q = tid + i * 256; int row = q >> 3, kq = q & 7;
            cpa16(stg + 16384 + sw128((uint32_t)(row * 128 + kq * 16)),
                  Bs + (size_t)row * KD + kb + kq * 8);
        }
        CPA_COMMIT();
    };

    float acc[2][8][4];
    #pragma unroll
    for (int mi = 0; mi < 2; mi++)
        #pragma unroll
        for (int ni = 0; ni < 8; ni++)
            #pragma unroll
            for (int q = 0; q < 4; q++) acc[mi][ni][q] = 0.0f;

    issue(0);
    issue(1);

    for (int it = 0; it < 48; it++) {
        if (it < 47) cp_wait<1>(); else cp_wait<0>();
        __syncthreads();
        if (it + 2 < 48) issue(it + 2);

        const uint32_t stg = smb + (it % 3) * P1_STG;
        #pragma unroll
        for (int kk = 0; kk < 4; kk++) {
            uint32_t af[2][4];
            {
                int tile = lane >> 3, r = lane & 7;
                int kb = kk * 32 + (tile >> 1) * 16;
                #pragma unroll
                for (int mi = 0; mi < 2; mi++) {
                    uint32_t sa = sw128((uint32_t)((wm * 32 + mi * 16 + (tile & 1) * 8 + r) * 128 + kb));
                    ldsm4(af[mi], stg + sa);
                }
            }
            uint32_t bfr[4][4];
            {
                int pair = lane >> 4, khalf = (lane >> 3) & 1, r = lane & 7;
                int kb = kk * 32 + khalf * 16;
                #pragma unroll
                for (int bp = 0; bp < 4; bp++) {
                    uint32_t sb = sw128((uint32_t)((wn * 64 + bp * 16 + pair * 8 + r) * 128 + kb));
                    ldsm4(bfr[bp], stg + 16384 + sb);
                }
            }
            #pragma unroll
            for (int mi = 0; mi < 2; mi++)
                #pragma unroll
                for (int ni = 0; ni < 8; ni++)
                    mma16816(acc[mi][ni], af[mi],
                             bfr[ni >> 1][(ni & 1) * 2], bfr[ni >> 1][(ni & 1) * 2 + 1]);
        }
    }

    const float* bias = (g == 0) ? b0p : (g == 1) ? b1p : b2p;
    float* C = g_gx + (size_t)g * MX * ND;
    #pragma unroll
    for (int ni = 0; ni < 8; ni++) {
        int col = n0 + wn * 64 + ni * 8 + (lane & 3) * 2;
        float2 bv = *(const float2*)(bias + col);
        #pragma unroll
        for (int mi = 0; mi < 2; mi++) {
            int row = m0 + wm * 32 + mi * 16 + (lane >> 2);
            float2 v0 = make_float2(acc[mi][ni][0] + bv.x, acc[mi][ni][1] + bv.y);
            float2 v1 = make_float2(acc[mi][ni][2] + bv.x, acc[mi][ni][3] + bv.y);
            *(float2*)(C + (size_t)row * ND + col)       = v0;
            *(float2*)(C + (size_t)(row + 8) * ND + col) = v1;
        }
    }
}

// ---------------- phase 2: persistent HMMA recurrence, k-split warps --------
// 8 warps = 2 kh x 2 wm x 2 wn. Warp tile: m32 x n48 x k32-per-chunk.
// Smem read/chunk: A 16K x2 + B 24K x2 = 80KB (was 128KB). 3-stage pipeline.
#define RST    40960                     // AH 8K | AL 8K | BH 12K | BL 12K
#define OFF_AL 8192
#define OFF_BH 16384
#define OFF_BL 28672
#define GH_OFF (3 * RST)                 // fp32 gh tiles [2][64][100]
#define HX_OFF (GH_OFF + 51200)          // fp32 [4][64][32]
#define SM2_TOTAL (HX_OFF + 32768)       // 206848 bytes

__global__ void bar_init_kernel() {
    #pragma unroll
    for (int i = 0; i < 4; i++) { g_cntArr[i * 32] = 0; g_genArr[i * 32] = 0; }
}

__global__ __launch_bounds__(256, 1)
void gru_persistent(const float* __restrict__ h0,
                    const float* __restrict__ brh, const float* __restrict__ buh,
                    const float* __restrict__ bch,
                    float* __restrict__ hseq, float* __restrict__ hlast)
{
    extern __shared__ char sm[];
    const uint32_t smb = smem_u32(sm);
    float* ghs = (float*)(sm + GH_OFF);
    float* hxs = (float*)(sm + HX_OFF);

    const int tid  = threadIdx.x;
    const int lane = tid & 31;
    const int w    = tid >> 5;
    const int kh   = w >> 2;             // k-half of each chunk
    const int wm   = w & 1;              // m half (32 rows)
    const int wn   = (w >> 1) & 1;       // n half (48 cols)
    const int c    = blockIdx.x;
    const int mb   = c & 3;
    const int r0   = mb * 64;
    const int jg   = c >> 2;
    const int n0   = jg * 32;

    const __nv_bfloat16* wph = g_wph + (size_t)(jg * 96) * KD;
    const __nv_bfloat16* wpl = g_wpl + (size_t)(jg * 96) * KD;
    const __nv_bfloat16* hhi = g_hhi + (size_t)r0 * KD;
    const __nv_bfloat16* hlo = g_hlo + (size_t)r0 * KD;

    const int jj = tid & 31;
    const float br_ = brh[n0 + jj], bu_ = buh[n0 + jj], bc_ = bch[n0 + jj];

    auto issue = [&](int ck) {
        uint32_t stg = smb + (ck % 3) * RST;
        int kb = ck * 64;
        #pragma unroll
        for (int i = 0; i < 2; i++) {
            int q = tid + i * 256; int row = q >> 3, kq = q & 7;
            uint32_t d = stg + sw128((uint32_t)(row * 128 + kq * 16));
            cpa16(d,          hhi + (size_t)row * KD + kb + kq * 8);
            cpa16(d + OFF_AL, hlo + (size_t)row * KD + kb + kq * 8);
        }
        #pragma unroll
        for (int i = 0; i < 3; i++) {
            int q = tid + i * 256; int row = q >> 3, kq = q & 7;
            uint32_t d = stg + OFF_BH + sw128((uint32_t)(row * 128 + kq * 16));
            cpa16(d,         wph + (size_t)row * KD + kb + kq * 8);
            cpa16(d + 12288, wpl + (size_t)row * KD + kb + kq * 8);
        }
        CPA_COMMIT();
    };

    auto issueW01 = [&]() {
        #pragma unroll
        for (int s = 0; s < 2; s++) {
            uint32_t stg = smb + s * RST;
            int kb = s * 64;
            #pragma unroll
            for (int i = 0; i < 3; i++) {
                int q = tid + i * 256; int row = q >> 3, kq = q & 7;
                uint32_t d = stg + OFF_BH + sw128((uint32_t)(row * 128 + kq * 16));
                cpa16(d,         wph + (size_t)row * KD + kb + kq * 8);
                cpa16(d + 12288, wpl + (size_t)row * KD + kb + kq * 8);
            }
        }
        CPA_COMMIT();
    };

    float acc[2][6][4];

    issueW01();

    for (int t = 0; t < SEQ; t++) {
        const float* hp = (t == 0) ? h0 : (hseq + (size_t)(t - 1) * HN);

        #pragma unroll
        for (int mi = 0; mi < 2; mi++)
            #pragma unroll
            for (int ni = 0; ni < 6; ni++)
                #pragma unroll
                for (int q = 0; q < 4; q++) acc[mi][ni][q] = 0.0f;

        // ---- G_h0: h chunk 0 + epilogue operands ----
        {
            uint32_t stg = smb;
            #pragma unroll
            for (int i = 0; i < 2; i++) {
                int q = tid + i * 256; int row = q >> 3, kq = q & 7;
                uint32_t d = stg + sw128((uint32_t)(row * 128 + kq * 16));
                cpa16(d,          hhi + (size_t)row * KD + kq * 8);
                cpa16(d + OFF_AL, hlo + (size_t)row * KD + kq * 8);
            }
            uint32_t hxb = smb + HX_OFF;
            #pragma unroll
            for (int g = 0; g < 3; g++) {
                const float* src = g_gx + (size_t)g * MX * ND
                                 + ((size_t)t * BATCH + r0) * ND + n0;
                #pragma unroll
                for (int i = 0; i < 2; i++) {
                    int q = tid + i * 256; int row = q >> 3, j4 = q & 7;
                    cpa16(hxb + g * 8192 + row * 128 + j4 * 16,
                          src + (size_t)row * ND + j4 * 4);
                }
            }
            #pragma unroll
            for (int i = 0; i < 2; i++) {
                int q = tid + i * 256; int row = q >> 3, j4 = q & 7;
                cpa16(hxb + 3 * 8192 + row * 128 + j4 * 16,
                      hp + (size_t)(r0 + row) * ND + n0 + j4 * 4);
            }
            CPA_COMMIT();
        }
        // ---- G_h1: h chunk 1 ----
        {
            uint32_t stg = smb + RST;
            #pragma unroll
            for (int i = 0; i < 2; i++) {
                int q = tid + i * 256; int row = q >> 3, kq = q & 7;
                uint32_t d = stg + sw128((uint32_t)(row * 128 + kq * 16));
                cpa16(d,          hhi + (size_t)row * KD + 64 + kq * 8);
                cpa16(d + OFF_AL, hlo + (size_t)row * KD + 64 + kq * 8);
            }
            CPA_COMMIT();
        }

        // ---- K loop: 16 chunks, 3 stages, issue AFTER sync (ring safety) ----
        for (int kt = 0; kt < 16; kt++) {
            if (kt < 15) cp_wait<1>(); else cp_wait<0>();
            __syncthreads();
            if (kt + 2 < 16) issue(kt + 2);

            const uint32_t stg = smb + (kt % 3) * RST;
            const int khb = kh * 64;     // byte offset of this warp's k-half
            #pragma unroll
            for (int kk = 0; kk < 2; kk++) {
                uint32_t ah[2][4], al[2][4], bh[3][4], bl[3][4];
                {
                    int tile = lane >> 3, r = lane & 7;
                    int kb = khb + kk * 32 + (tile >> 1) * 16;
                    #pragma unroll
                    for (int mi = 0; mi < 2; mi++) {
                        uint32_t sa = sw128((uint32_t)((wm * 32 + mi * 16 + (tile & 1) * 8 + r) * 128 + kb));
                        ldsm4(ah[mi], stg + sa);
                        ldsm4(al[mi], stg + OFF_AL + sa);
                    }
                }
                {
                    int pair = lane >> 4, khalf = (lane >> 3) & 1, r = lane & 7;
                    int kb = khb + kk * 32 + khalf * 16;
                    #pragma unroll
                    for (int bp = 0; bp < 3; bp++) {
                        uint32_t sb = sw128((uint32_t)((wn * 48 + bp * 16 + pair * 8 + r) * 128 + kb));
                        ldsm4(bh[bp], stg + OFF_BH + sb);
                        ldsm4(bl[bp], stg + OFF_BL + sb);
                    }
                }
                #pragma unroll
                for (int mi = 0; mi < 2; mi++)
                    #pragma unroll
                    for (int ni = 0; ni < 6; ni++) {
                        uint32_t b0h = bh[ni >> 1][(ni & 1) * 2], b1h = bh[ni >> 1][(ni & 1) * 2 + 1];
                        uint32_t b0l = bl[ni >> 1][(ni & 1) * 2], b1l = bl[ni >> 1][(ni & 1) * 2 + 1];
                        mma16816(acc[mi][ni], ah[mi], b0h, b1h);
                        mma16816(acc[mi][ni], al[mi], b0h, b1h);
                        mma16816(acc[mi][ni], ah[mi], b0l, b1l);
                    }
            }
        }

        // ---- dump per-k-half partials to ghs[kh] ----
        {
            float* gdst = ghs + kh * 6400;
            #pragma unroll
            for (int mi = 0; mi < 2; mi++)
                #pragma unroll
                for (int ni = 0; ni < 6; ni++) {
                    int col = wn * 48 + ni * 8 + (lane & 3) * 2;
                    int row = wm * 32 + mi * 16 + (lane >> 2);
                    *(float2*)(gdst + row * 100 + col)       = make_float2(acc[mi][ni][0], acc[mi][ni][1]);
                    *(float2*)(gdst + (row + 8) * 100 + col) = make_float2(acc[mi][ni][2], acc[mi][ni][3]);
                }
        }
        __syncthreads();

        // ---- fused gates: 8 rows per thread, sum the two k-half partials ----
        #pragma unroll 4
        for (int i = 0; i < 8; i++) {
            int row = (tid >> 5) * 8 + i;
            float pr  = ghs[row * 100 + jj]      + ghs[6400 + row * 100 + jj]
                      + hxs[0 * 2048 + row * 32 + jj] + br_;
            float pu  = ghs[row * 100 + 32 + jj] + ghs[6400 + row * 100 + 32 + jj]
                      + hxs[1 * 2048 + row * 32 + jj] + bu_;
            float pch = ghs[row * 100 + 64 + jj] + ghs[6400 + row * 100 + 64 + jj] + bc_;
            float xc  = hxs[2 * 2048 + row * 32 + jj];
            float hpv = hxs[3 * 2048 + row * 32 + jj];

            float rr = sigm(pr);
            float zz = sigm(pu);
            float nn = tanhf(xc + rr * pch);
            float hn = nn + zz * (hpv - nn);

            size_t gr = (size_t)(r0 + row) * ND + n0 + jj;
            hseq[(size_t)t * HN + gr] = hn;
            if (t == SEQ - 1) hlast[gr] = hn;
            __nv_bfloat16 hb = __float2bfloat16_rn(hn);
            g_hhi[gr] = hb;
            g_hlo[gr] = __float2bfloat16_rn(hn - __bfloat162float(hb));
        }

        // ---- prefetch next step's W chunks 0,1 ----
        __syncthreads();
        issueW01();

        // ---- group barrier (32 CTAs per m-block) ----
        if (tid == 0) {
            __threadfence();
            unsigned prev = atomicAdd(&g_cntArr[mb * 32], 1u);
            if (prev == 31u) {
                g_cntArr[mb * 32] = 0;
                __threadfence();
                atomicAdd(&g_genArr[mb * 32], 1u);
            } else {
                unsigned target = (unsigned)t + 1u;
                while (*(volatile unsigned*)&g_genArr[mb * 32] < target)
                    __nanosleep(20);
            }
        }
        __syncthreads();
    }
}

// ============================================================================
extern "C" void kernel_launch(void* const* d_in, const int* in_sizes, int n_in,
                              void* d_out, int out_size)
{
    const float* x   = (const float*)d_in[0];
    const float* h0  = (const float*)d_in[1];
    const float* Wrx = (const float*)d_in[2];
    const float* brx = (const float*)d_in[3];
    const float* Wrh = (const float*)d_in[4];
    const float* brh = (const float*)d_in[5];
    const float* Wux = (const float*)d_in[6];
    const float* bux = (const float*)d_in[7];
    const float* Wuh = (const float*)d_in[8];
    const float* buh = (const float*)d_in[9];
    const float* Wcx = (const float*)d_in[10];
    const float* bcx = (const float*)d_in[11];
    const float* Wch = (const float*)d_in[12];
    const float* bch = (const float*)d_in[13];

    float* out   = (float*)d_out;
    float* hseq  = out;
    float* hlast = out + (size_t)SEQ * BATCH * ND;

    __nv_bfloat16 *axhi, *axlo, *wxhi, *wxlo, *wph, *wpl, *hhi, *hlo;
    cudaGetSymbolAddress((void**)&axhi, g_axhi);
    cudaGetSymbolAddress((void**)&axlo, g_axlo);
    cudaGetSymbolAddress((void**)&wxhi, g_wxhi);
    cudaGetSymbolAddress((void**)&wxlo, g_wxlo);
    cudaGetSymbolAddress((void**)&wph,  g_wph);
    cudaGetSymbolAddress((void**)&wpl,  g_wpl);
    cudaGetSymbolAddress((void**)&hhi,  g_hhi);
    cudaGetSymbolAddress((void**)&hlo,  g_hlo);

    // Phase 0
    {
        int n4 = MX * KD / 4;
        split_bf16<<<(n4 + 255) / 256, 256>>>(x, axhi, axlo, n4);
        int w12 = 3 * ND * KD / 4;
        split3_w<<<(w12 + 255) / 256, 256>>>(Wrx, Wux, Wcx, wxhi, wxlo);
        pack3_wh<<<(w12 + 255) / 256, 256>>>(Wrh, Wuh, Wch, wph, wpl);
        int h4 = BATCH * KD / 4;
        split_bf16<<<(h4 + 255) / 256, 256>>>(h0, hhi, hlo, h4);
    }

    // Phase 1
    {
        const int smem_bytes = 3 * P1_STG;
        cudaFuncSetAttribute(gemm_hmma,
                             cudaFuncAttributeMaxDynamicSharedMemorySize, smem_bytes);
        dim3 grid(ND / 128, MX / 128, 3);
        gemm_hmma<<<grid, 256, smem_bytes>>>(brx, bux, bcx);
    }

    // Phase 2
    {
        cudaFuncSetAttribute(gru_persistent,
                             cudaFuncAttributeMaxDynamicSharedMemorySize, SM2_TOTAL);
        bar_init_kernel<<<1, 1>>>();
        gru_persistent<<<NCTA, 256, SM2_TOTAL>>>(h0, brh, buh, bch, hseq, hlast);
    }
}